// round 3
// baseline (speedup 1.0000x reference)
#include <cuda_runtime.h>
#include <cuda_bf16.h>
#include <math.h>

// ---------------------------------------------------------------------------
// Problem constants
// ---------------------------------------------------------------------------
#define BATCH 8192
#define DIN   4096
#define DMODEL 512
#define DFF   2048
#define NHEAD 3
#define HDIM  256
#define OUTD  896

// ---------------------------------------------------------------------------
// GEMM tiling
// ---------------------------------------------------------------------------
#define BM 128
#define BN 64
#define BK 32
#define STAGES 3
#define SA 36   // As row stride in floats (BK + 4): conflict-free fragment loads
#define SB 72   // Bs row stride in floats (BN + 8): conflict-free fragment loads
#define GEMM_THREADS 256
#define SMEM_FLOATS (STAGES * (BM * SA + BK * SB))
#define SMEM_BYTES  (SMEM_FLOATS * 4)

// ---------------------------------------------------------------------------
// Scratch (device globals; no allocation allowed)
// ---------------------------------------------------------------------------
__device__ float g_h0[BATCH * DMODEL];
__device__ float g_h [BATCH * DMODEL];
__device__ float g_lnb[BATCH * DMODEL];
__device__ float g_t [BATCH * DMODEL];
__device__ float g_ff[BATCH * DFF];
__device__ float g_z [BATCH * NHEAD * HDIM];
__device__ float g_z2[BATCH * NHEAD * HDIM];

// ---------------------------------------------------------------------------
// Helpers
// ---------------------------------------------------------------------------
__device__ __forceinline__ unsigned f2tf32(float f) {
    unsigned u;
    asm("cvt.rna.tf32.f32 %0, %1;" : "=r"(u) : "f"(f));
    return u;
}

__device__ __forceinline__ float gelu_exact(float v) {
    return 0.5f * v * (1.0f + erff(v * 0.7071067811865476f));
}

__device__ __forceinline__ void cp16(void* s, const void* g) {
    unsigned sa = (unsigned)__cvta_generic_to_shared(s);
    asm volatile("cp.async.cg.shared.global [%0], [%1], 16;" :: "r"(sa), "l"(g) : "memory");
}

__device__ __forceinline__ void mma_m16n8k8(float* d, const unsigned* a, const unsigned* b) {
    asm volatile(
        "mma.sync.aligned.m16n8k8.row.col.f32.tf32.tf32.f32 "
        "{%0,%1,%2,%3}, {%4,%5,%6,%7}, {%8,%9}, {%0,%1,%2,%3};"
        : "+f"(d[0]), "+f"(d[1]), "+f"(d[2]), "+f"(d[3])
        : "r"(a[0]), "r"(a[1]), "r"(a[2]), "r"(a[3]), "r"(b[0]), "r"(b[1]));
}

// ---------------------------------------------------------------------------
// TF32 GEMM: C[M,N] = A[M,K] @ B[K,N] (+bias +bias2 +residual, opt. exact gelu)
// A row-major lda, B row-major ldb, C row-major ldc. All dims divide tiles.
// ---------------------------------------------------------------------------
__global__ void __launch_bounds__(GEMM_THREADS)
gemm_tf32(const float* __restrict__ A, int lda,
          const float* __restrict__ B, int ldb,
          float* __restrict__ C, int ldc,
          const float* __restrict__ bias, const float* __restrict__ bias2,
          const float* __restrict__ resid, int ldres,
          int K, int dogelu)
{
    extern __shared__ float smem[];
    float* As = smem;
    float* Bs = smem + STAGES * BM * SA;

    const int tid  = threadIdx.x;
    const int warp = tid >> 5, lane = tid & 31;
    const int g = lane >> 2, tg = lane & 3;
    const int wm = warp & 3, wn = warp >> 2;          // 4 x 2 warp grid
    const int tile_m = blockIdx.y * BM;
    const int tile_n = blockIdx.x * BN;

    float acc[2][4][4];
    #pragma unroll
    for (int i = 0; i < 2; i++)
        #pragma unroll
        for (int j = 0; j < 4; j++)
            #pragma unroll
            for (int r = 0; r < 4; r++) acc[i][j][r] = 0.f;

    const int ktiles = K / BK;

    auto load_tiles = [&](int stage, int k0) {
        float* as = As + stage * BM * SA;
        float* bs = Bs + stage * BK * SB;
        #pragma unroll
        for (int i = 0; i < 4; i++) {                 // A: 128x32 = 1024 float4
            int idx = tid + i * GEMM_THREADS;
            int r = idx >> 3, q = idx & 7;
            cp16(as + r * SA + q * 4, A + (size_t)(tile_m + r) * lda + (k0 + q * 4));
        }
        #pragma unroll
        for (int i = 0; i < 2; i++) {                 // B: 32x64 = 512 float4
            int idx = tid + i * GEMM_THREADS;
            int r = idx >> 4, q = idx & 15;
            cp16(bs + r * SB + q * 4, B + (size_t)(k0 + r) * ldb + (tile_n + q * 4));
        }
    };

    #pragma unroll
    for (int s = 0; s < STAGES - 1; s++) {
        load_tiles(s, s * BK);
        asm volatile("cp.async.commit_group;" ::: "memory");
    }

    for (int kt = 0; kt < ktiles; kt++) {
        asm volatile("cp.async.wait_group %0;" :: "n"(STAGES - 2) : "memory");
        __syncthreads();
        const float* as = As + (kt % STAGES) * BM * SA;
        const float* bs = Bs + (kt % STAGES) * BK * SB;

        #pragma unroll
        for (int k8 = 0; k8 < BK / 8; k8++) {
            unsigned af[2][4], bf[4][2];
            #pragma unroll
            for (int mi = 0; mi < 2; mi++) {
                const float* ap = as + (wm * 32 + mi * 16 + g) * SA + k8 * 8 + tg;
                af[mi][0] = f2tf32(ap[0]);
                af[mi][1] = f2tf32(ap[8 * SA]);
                af[mi][2] = f2tf32(ap[4]);
                af[mi][3] = f2tf32(ap[8 * SA + 4]);
            }
            #pragma unroll
            for (int ni = 0; ni < 4; ni++) {
                const float* bp = bs + (k8 * 8 + tg) * SB + wn * 32 + ni * 8 + g;
                bf[ni][0] = f2tf32(bp[0]);
                bf[ni][1] = f2tf32(bp[4 * SB]);
            }
            #pragma unroll
            for (int mi = 0; mi < 2; mi++)
                #pragma unroll
                for (int ni = 0; ni < 4; ni++)
                    mma_m16n8k8(acc[mi][ni], af[mi], bf[ni]);
        }

        if (kt + STAGES - 1 < ktiles)
            load_tiles((kt + STAGES - 1) % STAGES, (kt + STAGES - 1) * BK);
        asm volatile("cp.async.commit_group;" ::: "memory");
    }

    // Epilogue
    #pragma unroll
    for (int mi = 0; mi < 2; mi++) {
        #pragma unroll
        for (int half = 0; half < 2; half++) {
            int row = tile_m + wm * 32 + mi * 16 + g + half * 8;
            #pragma unroll
            for (int ni = 0; ni < 4; ni++) {
                int n = tile_n + wn * 32 + ni * 8 + tg * 2;
                float v0 = acc[mi][ni][half * 2 + 0];
                float v1 = acc[mi][ni][half * 2 + 1];
                if (bias)  { v0 += bias[n];  v1 += bias[n + 1]; }
                if (bias2) { v0 += bias2[n]; v1 += bias2[n + 1]; }
                if (resid) {
                    const float* rr = resid + (size_t)row * ldres + n;
                    v0 += rr[0]; v1 += rr[1];
                }
                if (dogelu) { v0 = gelu_exact(v0); v1 = gelu_exact(v1); }
                float* cc = C + (size_t)row * ldc + n;
                cc[0] = v0; cc[1] = v1;
            }
        }
    }
}

// ---------------------------------------------------------------------------
// Block reduction for (sum, sumsq)
// ---------------------------------------------------------------------------
__device__ __forceinline__ void blockreduce2(float& s, float& q, float* red, int nwarps) {
    #pragma unroll
    for (int o = 16; o > 0; o >>= 1) {
        s += __shfl_xor_sync(0xFFFFFFFFu, s, o);
        q += __shfl_xor_sync(0xFFFFFFFFu, q, o);
    }
    int warp = threadIdx.x >> 5, lane = threadIdx.x & 31;
    if (lane == 0) { red[warp] = s; red[warp + 8] = q; }
    __syncthreads();
    s = 0.f; q = 0.f;
    for (int w = 0; w < nwarps; w++) { s += red[w]; q += red[w + 8]; }
}

// LayerNorm over D=512, one block (128 threads) per row, float4 per thread.
__global__ void ln512(const float* __restrict__ x, float* __restrict__ y,
                      const float* __restrict__ gam, const float* __restrict__ bet)
{
    __shared__ float red[16];
    int row = blockIdx.x;
    const float4* xr = (const float4*)(x + (size_t)row * DMODEL);
    float4 a = xr[threadIdx.x];
    float s = a.x + a.y + a.z + a.w;
    float q = a.x * a.x + a.y * a.y + a.z * a.z + a.w * a.w;
    blockreduce2(s, q, red, 4);
    float m  = s * (1.f / DMODEL);
    float va = q * (1.f / DMODEL) - m * m;
    float rs = rsqrtf(va + 1e-5f);
    float4 gg = ((const float4*)gam)[threadIdx.x];
    float4 bb = ((const float4*)bet)[threadIdx.x];
    float4 o;
    o.x = (a.x - m) * rs * gg.x + bb.x;
    o.y = (a.y - m) * rs * gg.y + bb.y;
    o.z = (a.z - m) * rs * gg.z + bb.z;
    o.w = (a.w - m) * rs * gg.w + bb.w;
    ((float4*)(y + (size_t)row * DMODEL))[threadIdx.x] = o;
}

// Per-head: gelu then LayerNorm over HD=256. grid(B, NH), 256 threads.
__global__ void head_gelu_ln(const float* __restrict__ z, float* __restrict__ y,
                             const float* __restrict__ gam, const float* __restrict__ bet)
{
    __shared__ float red[16];
    int b = blockIdx.x, h = blockIdx.y;
    int idx = b * (NHEAD * HDIM) + h * HDIM + threadIdx.x;
    float v = gelu_exact(z[idx]);
    float s = v, q = v * v;
    blockreduce2(s, q, red, 8);
    float m  = s * (1.f / HDIM);
    float va = q * (1.f / HDIM) - m * m;
    float rs = rsqrtf(va + 1e-5f);
    y[idx] = (v - m) * rs * gam[h * HDIM + threadIdx.x] + bet[h * HDIM + threadIdx.x];
}

// ---------------------------------------------------------------------------
// Launch
// ---------------------------------------------------------------------------
extern "C" void kernel_launch(void* const* d_in, const int* in_sizes, int n_in,
                              void* d_out, int out_size)
{
    (void)in_sizes; (void)n_in; (void)out_size;
    const float* x       = (const float*)d_in[0];
    const float* w_in    = (const float*)d_in[1];
    const float* b_in    = (const float*)d_in[2];
    const float* pos     = (const float*)d_in[3];
    const float* ln1_g   = (const float*)d_in[4];
    const float* ln1_b   = (const float*)d_in[5];
    const float* wv_sa   = (const float*)d_in[6];
    const float* bv_sa   = (const float*)d_in[7];
    const float* wo_sa   = (const float*)d_in[8];
    const float* bo_sa   = (const float*)d_in[9];
    // d_in[10], d_in[11]: ln2_g, ln2_b (unused by the reference math)
    const float* wv_ca   = (const float*)d_in[12];
    const float* bv_ca   = (const float*)d_in[13];
    const float* wo_ca   = (const float*)d_in[14];
    const float* bo_ca   = (const float*)d_in[15];
    const float* ln3_g   = (const float*)d_in[16];
    const float* ln3_b   = (const float*)d_in[17];
    const float* w_ff1   = (const float*)d_in[18];
    const float* b_ff1   = (const float*)d_in[19];
    const float* w_ff2   = (const float*)d_in[20];
    const float* b_ff2   = (const float*)d_in[21];
    const float* lnout_g = (const float*)d_in[22];
    const float* lnout_b = (const float*)d_in[23];
    const float* wh1     = (const float*)d_in[24];
    const float* bh1     = (const float*)d_in[25];
    const float* lnh_g   = (const float*)d_in[26];
    const float* lnh_b   = (const float*)d_in[27];
    const float* wh2     = (const float*)d_in[28];
    const float* bh2     = (const float*)d_in[29];
    float* out = (float*)d_out;

    float *h0, *h, *lnb, *t, *ff, *z, *z2;
    cudaGetSymbolAddress((void**)&h0,  g_h0);
    cudaGetSymbolAddress((void**)&h,   g_h);
    cudaGetSymbolAddress((void**)&lnb, g_lnb);
    cudaGetSymbolAddress((void**)&t,   g_t);
    cudaGetSymbolAddress((void**)&ff,  g_ff);
    cudaGetSymbolAddress((void**)&z,   g_z);
    cudaGetSymbolAddress((void**)&z2,  g_z2);

    cudaFuncSetAttribute(gemm_tf32, cudaFuncAttributeMaxDynamicSharedMemorySize, SMEM_BYTES);

    auto G = [&](const float* A, int lda, const float* Bm, int ldb,
                 float* C, int ldc,
                 const float* b1, const float* b2, const float* res, int ldres,
                 int M, int N, int K, int dg) {
        dim3 grid(N / BN, M / BM);
        gemm_tf32<<<grid, GEMM_THREADS, SMEM_BYTES>>>(A, lda, Bm, ldb, C, ldc,
                                                      b1, b2, res, ldres, K, dg);
    };

    // 1. h0 = x @ w_in + b_in + pos
    G(x, DIN, w_in, DMODEL, h0, DMODEL, b_in, pos, nullptr, 0, BATCH, DMODEL, DIN, 0);
    // 2. lnb = LN(h0; ln1)
    ln512<<<BATCH, 128>>>(h0, lnb, ln1_g, ln1_b);
    // 3. t = lnb @ wv_sa + bv_sa
    G(lnb, DMODEL, wv_sa, DMODEL, t, DMODEL, bv_sa, nullptr, nullptr, 0, BATCH, DMODEL, DMODEL, 0);
    // 4. h = h0 + t @ wo_sa + bo_sa
    G(t, DMODEL, wo_sa, DMODEL, h, DMODEL, bo_sa, nullptr, h0, DMODEL, BATCH, DMODEL, DMODEL, 0);
    // 5. t = h0 @ wv_ca + bv_ca   (cross-attn V on memory = h0)
    G(h0, DMODEL, wv_ca, DMODEL, t, DMODEL, bv_ca, nullptr, nullptr, 0, BATCH, DMODEL, DMODEL, 0);
    // 6. h = h + t @ wo_ca + bo_ca
    G(t, DMODEL, wo_ca, DMODEL, h, DMODEL, bo_ca, nullptr, h, DMODEL, BATCH, DMODEL, DMODEL, 0);
    // 7. lnb = LN(h; ln3)
    ln512<<<BATCH, 128>>>(h, lnb, ln3_g, ln3_b);
    // 8. ff = gelu(lnb @ w_ff1 + b_ff1)
    G(lnb, DMODEL, w_ff1, DFF, ff, DFF, b_ff1, nullptr, nullptr, 0, BATCH, DFF, DMODEL, 1);
    // 9. h = h + ff @ w_ff2 + b_ff2
    G(ff, DFF, w_ff2, DMODEL, h, DMODEL, b_ff2, nullptr, h, DMODEL, BATCH, DMODEL, DFF, 0);
    // 10. lnb = LN(h; lnout)
    ln512<<<BATCH, 128>>>(h, lnb, lnout_g, lnout_b);
    // 11. z[:, h*256:(h+1)*256] = lnb @ wh1[h] + bh1[h]
    for (int hh = 0; hh < NHEAD; hh++)
        G(lnb, DMODEL, wh1 + (size_t)hh * DMODEL * HDIM, HDIM,
          z + hh * HDIM, NHEAD * HDIM,
          bh1 + hh * HDIM, nullptr, nullptr, 0, BATCH, HDIM, DMODEL, 0);
    // 12. z2 = LN(gelu(z)) per head
    head_gelu_ln<<<dim3(BATCH, NHEAD), 256>>>(z, z2, lnh_g, lnh_b);
    // 13. out[:, h, :] = z2[:, h*256:...] @ wh2[h] + bh2[h]
    for (int hh = 0; hh < NHEAD; hh++)
        G(z2 + hh * HDIM, NHEAD * HDIM, wh2 + (size_t)hh * HDIM * OUTD, OUTD,
          out + hh * OUTD, NHEAD * OUTD,
          bh2 + hh * OUTD, nullptr, nullptr, 0, BATCH, OUTD, HDIM, 0);
}

// round 6
// speedup vs baseline: 1.0836x; 1.0836x over previous
#include <cuda_runtime.h>
#include <math.h>
#include <stdint.h>

// ---------------------------------------------------------------------------
// Problem constants
// ---------------------------------------------------------------------------
#define BATCH 8192
#define DIN   4096
#define DMODEL 512
#define DFF   2048
#define NHEAD 3
#define HDIM  256
#define OUTD  896

// ---------------------------------------------------------------------------
// HMMA tf32 GEMM tiling: 128x128x32, 512 threads, warp tile 32x32
// ---------------------------------------------------------------------------
#define BM 128
#define BN 128
#define BK 32
#define NSTAGE 4              // prefetch distance 2: no overwrite race
#define NTH 512
#define TILE_F 4096           // floats per operand tile (128*32)
#define STAGE_F (2*TILE_F)
#define SMEM_BYTES (NSTAGE * STAGE_F * 4)   // 131072

// ---------------------------------------------------------------------------
// Scratch (device globals; no allocation allowed)
// ---------------------------------------------------------------------------
__device__ float g_h0 [BATCH * DMODEL];
__device__ float g_h0r[BATCH * DMODEL];   // permuted+rounded copy of h0
__device__ float g_h  [BATCH * DMODEL];
__device__ float g_lnb[BATCH * DMODEL];   // permuted
__device__ float g_t  [BATCH * DMODEL];   // permuted
__device__ float g_ff [BATCH * DFF];      // permuted
__device__ float g_z  [BATCH * NHEAD * HDIM];
__device__ float g_z2 [BATCH * NHEAD * HDIM];  // permuted

// transposed + tf32-rounded + k-permuted weights [N,K]
#define OFF_WIN  0
#define OFF_WVSA 2097152
#define OFF_WOSA 2359296
#define OFF_WVCA 2621440
#define OFF_WOCA 2883584
#define OFF_FF1  3145728
#define OFF_FF2  4194304
#define OFF_WH1  5242880
#define OFF_WH2  5636096
#define WT_TOTAL 6324224
__device__ float g_wt[WT_TOTAL];

// ---------------------------------------------------------------------------
// Helpers
// ---------------------------------------------------------------------------
__device__ __forceinline__ float tf32r(float f) {
    unsigned u;
    asm("cvt.rna.tf32.f32 %0, %1;" : "=r"(u) : "f"(f));
    return __uint_as_float(u);
}
__device__ __forceinline__ unsigned f2u(float f) { return __float_as_uint(f); }

__device__ __forceinline__ float gelu_exact(float v) {
    return 0.5f * v * (1.0f + erff(v * 0.7071067811865476f));
}

// permuted position of column/k index c within its 32-block:
// p = (c%4)*8 + ((c%32)/8)*2 + ((c/4)%2)
__device__ __forceinline__ int permcol(int c) {
    return (c & ~31) + ((c & 3) * 8 + ((c & 31) >> 3) * 2 + ((c >> 2) & 1));
}

__device__ __forceinline__ uint32_t smem_u32(const void* p) {
    uint32_t a;
    asm("{ .reg .u64 t; cvta.to.shared.u64 t, %1; cvt.u32.u64 %0, t; }" : "=r"(a) : "l"(p));
    return a;
}
__device__ __forceinline__ void cp16(uint32_t s, const void* g) {
    asm volatile("cp.async.cg.shared.global [%0], [%1], 16;" :: "r"(s), "l"(g) : "memory");
}

#define MMA(d, a0,a1,a2,a3, b0,b1) \
    asm volatile("mma.sync.aligned.m16n8k8.row.col.f32.tf32.tf32.f32 " \
        "{%0,%1,%2,%3},{%4,%5,%6,%7},{%8,%9},{%0,%1,%2,%3};" \
        : "+f"((d)[0]), "+f"((d)[1]), "+f"((d)[2]), "+f"((d)[3]) \
        : "r"(a0), "r"(a1), "r"(a2), "r"(a3), "r"(b0), "r"(b1))

// ---------------------------------------------------------------------------
// tf32 GEMM via mma.sync: C[M,N] = A[M,K] @ Bt[N,K]^T
// Bt: [N,K], tf32-rounded, k-permuted within 32-blocks (prepass).
// A: if PLAIN_A, plain fp32 row-major (rounded+permuted on load);
//    else already rounded + k-permuted (produced by LN / earlier epilogues).
// Epilogue: +bias(+z-stride) +bias2 +resid, optional gelu, optional tf32
// rounding, output plain or permuted, optional second permuted+rounded copy.
// ---------------------------------------------------------------------------
template<bool PLAIN_A>
__global__ void __launch_bounds__(NTH, 1)
gemm_mma(const float* __restrict__ A, int lda, int az,
         const float* __restrict__ Bt, int K, int bz,
         float* __restrict__ C, int ldc, int cz,
         float* __restrict__ Cr,
         const float* __restrict__ bias, int biasz,
         const float* __restrict__ bias2,
         const float* __restrict__ resid, int ldres,
         int dogelu, int doround, int permC)
{
    extern __shared__ float smemf[];
    const uint32_t sb = smem_u32(smemf);

    A  += (size_t)blockIdx.z * az;
    Bt += (size_t)blockIdx.z * bz;
    C  += (size_t)blockIdx.z * cz;
    if (bias) bias += (size_t)blockIdx.z * biasz;

    const int tid = threadIdx.x;
    const int wid = tid >> 5, lane = tid & 31;
    const int g = lane >> 2, tg = lane & 3;
    const int wm = wid & 3, wn = wid >> 2;        // 4x4 warp grid
    const int tile_m = blockIdx.y * BM;
    const int tile_n = blockIdx.x * BN;
    const int ktiles = K / BK;

    // loader indices: each thread handles one row (lr) and one quarter (lj)
    const int lr = tid >> 2;                      // 0..127
    const int lj = tid & 3;                       // 0..3
    const int lsw = lr & 7;

    float acc[2][4][4];
    #pragma unroll
    for (int i = 0; i < 2; i++)
        #pragma unroll
        for (int j = 0; j < 4; j++)
            #pragma unroll
            for (int r = 0; r < 4; r++) acc[i][j][r] = 0.f;

    auto load_B = [&](int buf, int k0) {
        uint32_t dst = sb + (buf * STAGE_F + TILE_F + lr * 32) * 4;
        const float* src = Bt + (size_t)(tile_n + lr) * K + k0;
        cp16(dst + ((lj)     ^ lsw) * 16, src + lj * 4);
        cp16(dst + ((lj + 4) ^ lsw) * 16, src + (lj + 4) * 4);
    };
    auto load_A_perm = [&](int buf, int k0) {
        uint32_t dst = sb + (buf * STAGE_F + lr * 32) * 4;
        const float* src = A + (size_t)(tile_m + lr) * lda + k0;
        cp16(dst + ((lj)     ^ lsw) * 16, src + lj * 4);
        cp16(dst + ((lj + 4) ^ lsw) * 16, src + (lj + 4) * 4);
    };
    auto ldg_A = [&](int k0, float4& u, float4& v) {
        const float* src = A + (size_t)(tile_m + lr) * lda + k0 + lj * 8;
        u = *(const float4*)src;
        v = *(const float4*)(src + 4);
    };
    auto sts_A = [&](int buf, float4 u, float4 v) {
        // permuted scatter: pair (u[t], v[t]) -> position t*8 + lj*2
        float* base = smemf + buf * STAGE_F + lr * 32;
        int sub = (lj & 1) * 2;
        const float* up = (const float*)&u;
        const float* vp = (const float*)&v;
        #pragma unroll
        for (int t = 0; t < 4; t++) {
            int gi = (2 * t + (lj >> 1)) ^ lsw;
            *(float2*)(base + gi * 4 + sub) =
                make_float2(tf32r(up[t]), tf32r(vp[t]));
        }
    };

    // ---- prologue: stages 0, 1 ----
    #pragma unroll
    for (int s = 0; s < 2; s++) {
        if (PLAIN_A) {
            float4 u, v;
            ldg_A(s * BK, u, v);
            sts_A(s, u, v);
        } else {
            load_A_perm(s, s * BK);
        }
        load_B(s, s * BK);
        asm volatile("cp.async.commit_group;" ::: "memory");
    }

    // ---- main loop ----
    for (int kt = 0; kt < ktiles; kt++) {
        asm volatile("cp.async.wait_group 1;" ::: "memory");
        __syncthreads();

        const int pf = kt + 2;
        float4 u, v;
        if (PLAIN_A && pf < ktiles) ldg_A(pf * BK, u, v);  // overlap with MMA

        const float* as = smemf + (kt % NSTAGE) * STAGE_F;
        const float* bs = as + TILE_F;

        #pragma unroll
        for (int j2 = 0; j2 < 2; j2++) {
            const int gsw = ((2 * tg + j2) ^ g) * 4;
            float4 af[2][2], bf[4];
            #pragma unroll
            for (int mi = 0; mi < 2; mi++) {
                const int r0 = wm * 32 + mi * 16 + g;
                af[mi][0] = *(const float4*)(as + r0 * 32 + gsw);
                af[mi][1] = *(const float4*)(as + (r0 + 8) * 32 + gsw);
            }
            #pragma unroll
            for (int ni = 0; ni < 4; ni++) {
                const int n0 = wn * 32 + ni * 8 + g;
                bf[ni] = *(const float4*)(bs + n0 * 32 + gsw);
            }
            #pragma unroll
            for (int ni = 0; ni < 4; ni++)
                #pragma unroll
                for (int mi = 0; mi < 2; mi++) {
                    MMA(acc[mi][ni],
                        f2u(af[mi][0].x), f2u(af[mi][1].x),
                        f2u(af[mi][0].y), f2u(af[mi][1].y),
                        f2u(bf[ni].x), f2u(bf[ni].y));
                    MMA(acc[mi][ni],
                        f2u(af[mi][0].z), f2u(af[mi][1].z),
                        f2u(af[mi][0].w), f2u(af[mi][1].w),
                        f2u(bf[ni].z), f2u(bf[ni].w));
                }
        }

        if (pf < ktiles) {
            const int buf = pf % NSTAGE;
            if (PLAIN_A) sts_A(buf, u, v);
            else         load_A_perm(buf, pf * BK);
            load_B(buf, pf * BK);
        }
        asm volatile("cp.async.commit_group;" ::: "memory");
    }

    // ---- epilogue ----
    #pragma unroll
    for (int mi = 0; mi < 2; mi++) {
        const int rbase = tile_m + wm * 32 + mi * 16 + g;
        #pragma unroll
        for (int rr = 0; rr < 2; rr++) {
            const int row = rbase + rr * 8;
            const float* resrow = resid ? resid + (size_t)row * ldres : nullptr;
            float* crow  = C + (size_t)row * ldc;
            float* crrow = Cr ? Cr + (size_t)row * ldc : nullptr;
            #pragma unroll
            for (int ni = 0; ni < 4; ni++) {
                const int c = tile_n + wn * 32 + ni * 8 + tg * 2;
                float v0 = acc[mi][ni][rr * 2 + 0];
                float v1 = acc[mi][ni][rr * 2 + 1];
                if (bias)   { v0 += bias[c];   v1 += bias[c + 1]; }
                if (bias2)  { v0 += bias2[c];  v1 += bias2[c + 1]; }
                if (resrow) { v0 += resrow[c]; v1 += resrow[c + 1]; }
                if (dogelu) { v0 = gelu_exact(v0); v1 = gelu_exact(v1); }
                if (doround){ v0 = tf32r(v0); v1 = tf32r(v1); }
                if (permC) {
                    crow[permcol(c)]     = v0;
                    crow[permcol(c + 1)] = v1;
                } else {
                    *(float2*)(crow + c) = make_float2(v0, v1);
                }
                if (crrow) {
                    crrow[permcol(c)]     = tf32r(v0);
                    crrow[permcol(c + 1)] = tf32r(v1);
                }
            }
        }
    }
}

// ---------------------------------------------------------------------------
// Weight prepass: ONE launch. W[K,N] -> Wt[N,K], tf32 rounded, k-permuted.
// ---------------------------------------------------------------------------
#define NWT 13
struct TTable {
    const float* W[NWT];
    float*       Wt[NWT];
    int K[NWT], N[NWT], t0[NWT];
};

__global__ void __launch_bounds__(256)
transpose_all(TTable tab)
{
    __shared__ float ts[32][33];
    int bid = blockIdx.x;
    int e = 0;
    #pragma unroll
    for (int i = 1; i < NWT; i++)
        if (bid >= tab.t0[i]) e = i;
    int t  = bid - tab.t0[e];
    int nx = tab.N[e] >> 5;
    int n0 = (t % nx) << 5, k0 = (t / nx) << 5;
    const float* W = tab.W[e];
    float* Wt = tab.Wt[e];
    int K = tab.K[e], N = tab.N[e];
    int tx = threadIdx.x & 31, ty = threadIdx.x >> 5;   // 32 x 8
    #pragma unroll
    for (int j = 0; j < 32; j += 8)
        ts[ty + j][tx] = W[(size_t)(k0 + ty + j) * N + n0 + tx];
    __syncthreads();
    int pp = (tx & 3) * 8 + (tx >> 3) * 2 + ((tx >> 2) & 1);  // permuted pos of k=tx
    #pragma unroll
    for (int j = 0; j < 32; j += 8)
        Wt[(size_t)(n0 + ty + j) * K + k0 + pp] = tf32r(ts[tx][ty + j]);
}

// ---------------------------------------------------------------------------
// LayerNorms (outputs rounded + k-permuted: they always feed GEMM A operands)
// ---------------------------------------------------------------------------
__device__ __forceinline__ void blockreduce2(float& s, float& q, float* red, int nwarps) {
    #pragma unroll
    for (int o = 16; o > 0; o >>= 1) {
        s += __shfl_xor_sync(0xFFFFFFFFu, s, o);
        q += __shfl_xor_sync(0xFFFFFFFFu, q, o);
    }
    int warp = threadIdx.x >> 5, lane = threadIdx.x & 31;
    if (lane == 0) { red[warp] = s; red[warp + 8] = q; }
    __syncthreads();
    s = 0.f; q = 0.f;
    for (int w = 0; w < nwarps; w++) { s += red[w]; q += red[w + 8]; }
}

__global__ void ln512(const float* __restrict__ x, float* __restrict__ y,
                      const float* __restrict__ gam, const float* __restrict__ bet)
{
    __shared__ float red[16];
    int row = blockIdx.x;
    int t = threadIdx.x;                          // 128 threads, float4 each
    const float4* xr = (const float4*)(x + (size_t)row * DMODEL);
    float4 a = xr[t];
    float s = a.x + a.y + a.z + a.w;
    float q = a.x * a.x + a.y * a.y + a.z * a.z + a.w * a.w;
    blockreduce2(s, q, red, 4);
    float m  = s * (1.f / DMODEL);
    float va = q * (1.f / DMODEL) - m * m;
    float rs = rsqrtf(va + 1e-5f);
    float4 gg = ((const float4*)gam)[t];
    float4 bb = ((const float4*)bet)[t];
    float o[4];
    o[0] = tf32r((a.x - m) * rs * gg.x + bb.x);
    o[1] = tf32r((a.y - m) * rs * gg.y + bb.y);
    o[2] = tf32r((a.z - m) * rs * gg.z + bb.z);
    o[3] = tf32r((a.w - m) * rs * gg.w + bb.w);
    // permuted scatter: cols c = t*4 + i
    float* yr = y + (size_t)row * DMODEL;
    #pragma unroll
    for (int i = 0; i < 4; i++) yr[permcol(t * 4 + i)] = o[i];
}

__global__ void head_gelu_ln(const float* __restrict__ z, float* __restrict__ y,
                             const float* __restrict__ gam, const float* __restrict__ bet)
{
    __shared__ float red[16];
    int b = blockIdx.x, h = blockIdx.y;
    int c = threadIdx.x;                           // 256 threads
    int base = b * (NHEAD * HDIM) + h * HDIM;
    float v = gelu_exact(z[base + c]);
    float s = v, q = v * v;
    blockreduce2(s, q, red, 8);
    float m  = s * (1.f / HDIM);
    float va = q * (1.f / HDIM) - m * m;
    float rs = rsqrtf(va + 1e-5f);
    float o = tf32r((v - m) * rs * gam[h * HDIM + c] + bet[h * HDIM + c]);
    y[base + permcol(c)] = o;
}

// ---------------------------------------------------------------------------
// Launch
// ---------------------------------------------------------------------------
extern "C" void kernel_launch(void* const* d_in, const int* in_sizes, int n_in,
                              void* d_out, int out_size)
{
    (void)in_sizes; (void)n_in; (void)out_size;
    const float* x       = (const float*)d_in[0];
    const float* w_in    = (const float*)d_in[1];
    const float* b_in    = (const float*)d_in[2];
    const float* pos     = (const float*)d_in[3];
    const float* ln1_g   = (const float*)d_in[4];
    const float* ln1_b   = (const float*)d_in[5];
    const float* wv_sa   = (const float*)d_in[6];
    const float* bv_sa   = (const float*)d_in[7];
    const float* wo_sa   = (const float*)d_in[8];
    const float* bo_sa   = (const float*)d_in[9];
    const float* wv_ca   = (const float*)d_in[12];
    const float* bv_ca   = (const float*)d_in[13];
    const float* wo_ca   = (const float*)d_in[14];
    const float* bo_ca   = (const float*)d_in[15];
    const float* ln3_g   = (const float*)d_in[16];
    const float* ln3_b   = (const float*)d_in[17];
    const float* w_ff1   = (const float*)d_in[18];
    const float* b_ff1   = (const float*)d_in[19];
    const float* w_ff2   = (const float*)d_in[20];
    const float* b_ff2   = (const float*)d_in[21];
    const float* lnout_g = (const float*)d_in[22];
    const float* lnout_b = (const float*)d_in[23];
    const float* wh1     = (const float*)d_in[24];
    const float* bh1     = (const float*)d_in[25];
    const float* lnh_g   = (const float*)d_in[26];
    const float* lnh_b   = (const float*)d_in[27];
    const float* wh2     = (const float*)d_in[28];
    const float* bh2     = (const float*)d_in[29];
    float* out = (float*)d_out;

    float *h0, *h0r, *h, *lnb, *t, *ff, *z, *z2, *wt;
    cudaGetSymbolAddress((void**)&h0,  g_h0);
    cudaGetSymbolAddress((void**)&h0r, g_h0r);
    cudaGetSymbolAddress((void**)&h,   g_h);
    cudaGetSymbolAddress((void**)&lnb, g_lnb);
    cudaGetSymbolAddress((void**)&t,   g_t);
    cudaGetSymbolAddress((void**)&ff,  g_ff);
    cudaGetSymbolAddress((void**)&z,   g_z);
    cudaGetSymbolAddress((void**)&z2,  g_z2);
    cudaGetSymbolAddress((void**)&wt,  g_wt);

    cudaFuncSetAttribute(gemm_mma<true>,
                         cudaFuncAttributeMaxDynamicSharedMemorySize, SMEM_BYTES);
    cudaFuncSetAttribute(gemm_mma<false>,
                         cudaFuncAttributeMaxDynamicSharedMemorySize, SMEM_BYTES);

    // ---- weight prepass: ONE launch ----
    {
        TTable tab;
        int idx = 0, acc = 0;
        auto add = [&](const float* W, float* Wt, int K, int N) {
            tab.W[idx] = W; tab.Wt[idx] = Wt; tab.K[idx] = K; tab.N[idx] = N;
            tab.t0[idx] = acc; acc += (K / 32) * (N / 32); idx++;
        };
        add(w_in,  wt + OFF_WIN,  DIN,    DMODEL);
        add(wv_sa, wt + OFF_WVSA, DMODEL, DMODEL);
        add(wo_sa, wt + OFF_WOSA, DMODEL, DMODEL);
        add(wv_ca, wt + OFF_WVCA, DMODEL, DMODEL);
        add(wo_ca, wt + OFF_WOCA, DMODEL, DMODEL);
        add(w_ff1, wt + OFF_FF1,  DMODEL, DFF);
        add(w_ff2, wt + OFF_FF2,  DFF,    DMODEL);
        for (int hh = 0; hh < NHEAD; hh++)
            add(wh1 + (size_t)hh * DMODEL * HDIM,
                wt + OFF_WH1 + (size_t)hh * HDIM * DMODEL, DMODEL, HDIM);
        for (int hh = 0; hh < NHEAD; hh++)
            add(wh2 + (size_t)hh * HDIM * OUTD,
                wt + OFF_WH2 + (size_t)hh * OUTD * HDIM, HDIM, OUTD);
        transpose_all<<<acc, 256>>>(tab);
    }

    // G<plain>(A, lda, az, Bt, K, bz, C, ldc, cz, Cr, bias, biasz, bias2,
    //          resid, ldres, gelu, round, permC, M, N, nz)
    auto G = [&](bool plainA,
                 const float* A, int lda, int az,
                 const float* Bt, int K, int bz,
                 float* C, int ldc, int cz, float* Cr,
                 const float* b1, int b1z, const float* b2,
                 const float* res, int ldres,
                 int dg, int dr, int pc, int M, int N, int nz) {
        dim3 grid(N / BN, M / BM, nz);
        if (plainA)
            gemm_mma<true><<<grid, NTH, SMEM_BYTES>>>(A, lda, az, Bt, K, bz,
                C, ldc, cz, Cr, b1, b1z, b2, res, ldres, dg, dr, pc);
        else
            gemm_mma<false><<<grid, NTH, SMEM_BYTES>>>(A, lda, az, Bt, K, bz,
                C, ldc, cz, Cr, b1, b1z, b2, res, ldres, dg, dr, pc);
    };

    // 1. h0 = x @ w_in + b_in + pos (plain); h0r = rounded+permuted copy
    G(true, x, DIN, 0, wt + OFF_WIN, DIN, 0, h0, DMODEL, 0, h0r,
      b_in, 0, pos, nullptr, 0, 0, 0, 0, BATCH, DMODEL, 1);
    // 2. lnb = LN(h0; ln1)  (rounded + permuted)
    ln512<<<BATCH, 128>>>(h0, lnb, ln1_g, ln1_b);
    // 3. t = lnb @ wv_sa + bv_sa  (rounded + permuted)
    G(false, lnb, DMODEL, 0, wt + OFF_WVSA, DMODEL, 0, t, DMODEL, 0, nullptr,
      bv_sa, 0, nullptr, nullptr, 0, 0, 1, 1, BATCH, DMODEL, 1);
    // 4. h = h0 + t @ wo_sa + bo_sa  (plain)
    G(false, t, DMODEL, 0, wt + OFF_WOSA, DMODEL, 0, h, DMODEL, 0, nullptr,
      bo_sa, 0, nullptr, h0, DMODEL, 0, 0, 0, BATCH, DMODEL, 1);
    // 5. t = h0r @ wv_ca + bv_ca  (rounded + permuted)
    G(false, h0r, DMODEL, 0, wt + OFF_WVCA, DMODEL, 0, t, DMODEL, 0, nullptr,
      bv_ca, 0, nullptr, nullptr, 0, 0, 1, 1, BATCH, DMODEL, 1);
    // 6. h = h + t @ wo_ca + bo_ca  (in-place residual: same elem, same thread)
    G(false, t, DMODEL, 0, wt + OFF_WOCA, DMODEL, 0, h, DMODEL, 0, nullptr,
      bo_ca, 0, nullptr, h, DMODEL, 0, 0, 0, BATCH, DMODEL, 1);
    // 7. lnb = LN(h; ln3)
    ln512<<<BATCH, 128>>>(h, lnb, ln3_g, ln3_b);
    // 8. ff = gelu(lnb @ w_ff1 + b_ff1)  (rounded + permuted)
    G(false, lnb, DMODEL, 0, wt + OFF_FF1, DMODEL, 0, ff, DFF, 0, nullptr,
      b_ff1, 0, nullptr, nullptr, 0, 1, 1, 1, BATCH, DFF, 1);
    // 9. h = h + ff @ w_ff2 + b_ff2  (plain)
    G(false, ff, DFF, 0, wt + OFF_FF2, DFF, 0, h, DMODEL, 0, nullptr,
      b_ff2, 0, nullptr, h, DMODEL, 0, 0, 0, BATCH, DMODEL, 1);
    // 10. lnb = LN(h; lnout)
    ln512<<<BATCH, 128>>>(h, lnb, lnout_g, lnout_b);
    // 11. z[:, hh] = lnb @ wh1[hh] + bh1[hh]  — batched over heads (plain out)
    G(false, lnb, DMODEL, 0, wt + OFF_WH1, DMODEL, HDIM * DMODEL,
      z, NHEAD * HDIM, HDIM, nullptr,
      bh1, HDIM, nullptr, nullptr, 0, 0, 0, 0, BATCH, HDIM, NHEAD);
    // 12. z2 = LN(gelu(z)) per head  (rounded + permuted)
    head_gelu_ln<<<dim3(BATCH, NHEAD), 256>>>(z, z2, lnh_g, lnh_b);
    // 13. out[:, hh, :] = z2[:, hh] @ wh2[hh] + bh2[hh]  — batched (plain out)
    G(false, z2, NHEAD * HDIM, HDIM, wt + OFF_WH2, HDIM, OUTD * HDIM,
      out, NHEAD * OUTD, OUTD, nullptr,
      bh2, OUTD, nullptr, nullptr, 0, 0, 0, 0, BATCH, OUTD, NHEAD);
}